// round 4
// baseline (speedup 1.0000x reference)
#include <cuda_runtime.h>
#include <math.h>

#define B 64
#define T 2048
#define H 512
#define S 512
#define K 128
#define V 128
#define NS 32
#define CHUNK (T/NS)        // 64 rows per CTA
#define TILE 16             // rows per smem tile
#define FTHREADS 512

// ---- scratch (no device allocations allowed) ----
__device__ float g_q[B*K];        // query per batch
__device__ float g_c[B];          // q . bh
__device__ float g_w[B*H];        // folded query-key weight per batch
__device__ float g_e[B*T];        // energies (valid t only)
__device__ float g_pm[B*NS];      // partial max
__device__ float g_ps[B*NS];      // partial masked sum S
__device__ float g_pu[B*NS*H];    // partial weighted sums
__device__ float g_m[B];          // final max
__device__ float g_coef[B];       // 1/S

__device__ __forceinline__ void cp16(float* smem, const float* gmem) {
    unsigned s = (unsigned)__cvta_generic_to_shared(smem);
    asm volatile("cp.async.cg.shared.global [%0], [%1], 16;" :: "r"(s), "l"(gmem));
}

// ---------------- Kernel A1: q_b = Ws state_b + bs ; c_b = q.bh ----------------
__global__ void prep_q_kernel(const float* __restrict__ state,
                              const float* __restrict__ Ws, const float* __restrict__ bs,
                              const float* __restrict__ bh) {
    const int b = blockIdx.x, tid = threadIdx.x;   // 128 threads, one k each
    __shared__ float st[S];
    __shared__ float prod[K];
    #pragma unroll
    for (int i = 0; i < S/128; i++) st[tid + i*128] = state[b*S + tid + i*128];
    __syncthreads();
    const float4* wr  = (const float4*)(Ws + (size_t)tid*S);
    const float4* stv = (const float4*)st;
    float acc = 0.f;
    #pragma unroll 8
    for (int i = 0; i < S/4; i++) {
        float4 a = wr[i], x = stv[i];
        acc += a.x*x.x + a.y*x.y + a.z*x.z + a.w*x.w;
    }
    const float q = acc + bs[tid];
    g_q[b*K + tid] = q;
    prod[tid] = q * bh[tid];
    __syncthreads();
    if (tid == 0) {
        float c = 0.f;
        #pragma unroll 8
        for (int k = 0; k < K; k++) c += prod[k];
        g_c[b] = c;
    }
}

// ---------------- Kernel A2: w_b = Wh^T q_b ----------------
__global__ void prep_w_kernel(const float* __restrict__ Wh) {
    const int half = blockIdx.x, b = blockIdx.y;   // 256 threads, one h each
    const int tid = threadIdx.x;
    const int h = half*256 + tid;
    __shared__ float qs[K];
    if (tid < K) qs[tid] = g_q[b*K + tid];
    __syncthreads();
    float acc = 0.f;
    #pragma unroll 8
    for (int k = 0; k < K; k++) acc += Wh[(size_t)k*H + h] * qs[k];
    g_w[b*H + h] = acc;
}

// ---------------- Kernel B: flash pass (valid rows only) ----------------
// grid (NS, B), 512 threads, dynamic smem double-buffered cp.async tiles.
__global__ void __launch_bounds__(FTHREADS) flash_kernel(const float* __restrict__ x,
                                                         const int* __restrict__ lens) {
    extern __shared__ float sm[];
    float* buf0 = sm;                    // TILE*H
    float* buf1 = sm + TILE*H;           // TILE*H
    float* wsm  = sm + 2*TILE*H;         // H
    float* esm  = wsm + H;               // TILE
    float* psm  = esm + TILE;            // TILE

    const int split = blockIdx.x, b = blockIdx.y;
    const int tid = threadIdx.x;
    const int warp = tid >> 5, lane = tid & 31;

    int len = lens[b];
    if (b == 0) len = T;
    if (len > T) len = T;
    const int t0 = split * CHUNK;
    int rows = len - t0;
    if (rows > CHUNK) rows = CHUNK;
    const int pi = b*NS + split;
    if (rows <= 0) {
        if (tid == 0) { g_pm[pi] = -INFINITY; g_ps[pi] = 0.f; }
        g_pu[(size_t)pi*H + tid] = 0.f;
        return;
    }
    const int ntiles = (rows + TILE - 1) / TILE;

    const float* xb = x + (size_t)b*T*H + (size_t)t0*H;

    // prefetch tile 0 (always full TILE rows; in-bounds, finite data)
    {
        #pragma unroll
        for (int i = 0; i < (TILE*H/4)/FTHREADS; i++)
            cp16(buf0 + (tid + i*FTHREADS)*4, xb + (size_t)(tid + i*FTHREADS)*4);
        asm volatile("cp.async.commit_group;");
    }

    wsm[tid] = g_w[b*H + tid];
    const float cb = g_c[b];

    float m = -INFINITY, Ssum = 0.f, u = 0.f;

    for (int ti = 0; ti < ntiles; ti++) {
        float* tl = (ti & 1) ? buf1 : buf0;
        if (ti + 1 < ntiles) {
            float* dst = (ti & 1) ? buf0 : buf1;
            const float* src = xb + (size_t)(ti+1)*TILE*H;
            #pragma unroll
            for (int i = 0; i < (TILE*H/4)/FTHREADS; i++)
                cp16(dst + (tid + i*FTHREADS)*4, src + (size_t)(tid + i*FTHREADS)*4);
            asm volatile("cp.async.commit_group;");
            asm volatile("cp.async.wait_group 1;");
        } else {
            asm volatile("cp.async.wait_group 0;");
        }
        __syncthreads();

        // energy: one warp per row (16 warps, 16 rows)
        {
            const int r = warp;
            const float4* row = (const float4*)(tl + r*H);
            const float4* wv  = (const float4*)wsm;
            float acc = 0.f;
            #pragma unroll
            for (int i = 0; i < H/128; i++) {
                float4 a = row[lane + i*32], w = wv[lane + i*32];
                acc += a.x*w.x + a.y*w.y + a.z*w.z + a.w*w.w;
            }
            #pragma unroll
            for (int o = 16; o > 0; o >>= 1)
                acc += __shfl_xor_sync(0xffffffffu, acc, o);
            if (lane == 0) {
                const int t = t0 + ti*TILE + r;
                const float e = acc + cb;
                if (t < len) { esm[r] = e; g_e[b*T + t] = e; }
                else         { esm[r] = -INFINITY; }
            }
        }
        __syncthreads();
        // online softmax update (replicated; identical across threads)
        float tmax = esm[0];
        #pragma unroll
        for (int r = 1; r < TILE; r++) tmax = fmaxf(tmax, esm[r]);
        const float m_new = fmaxf(m, tmax);
        const float scale = __expf(m - m_new);
        u *= scale; Ssum *= scale;
        m = m_new;
        if (tid < TILE) psm[tid] = __expf(esm[tid] - m_new);  // exp(-inf)=0
        __syncthreads();
        #pragma unroll
        for (int r = 0; r < TILE; r++) {
            const float p = psm[r];
            Ssum += p;
            u += p * tl[r*H + tid];
        }
        __syncthreads();  // buffer free before it is prefetched again
    }

    g_pu[(size_t)pi*H + tid] = u;
    if (tid == 0) { g_pm[pi] = m; g_ps[pi] = Ssum; }
}

// ---------------- Kernel C1: reduce partials + context GEMV ----------------
// grid B, 512 threads: one h per thread, NS independent loads in flight.
__global__ void __launch_bounds__(512) reduce_kernel(const float* __restrict__ Wv,
                                                     const float* __restrict__ bv,
                                                     float* __restrict__ out) {
    const int b = blockIdx.x, tid = threadIdx.x;
    __shared__ float U[H];
    __shared__ float fac[NS];
    float m = -INFINITY;
    #pragma unroll
    for (int i = 0; i < NS; i++) m = fmaxf(m, g_pm[b*NS + i]);
    if (tid < NS) fac[tid] = __expf(g_pm[b*NS + tid] - m);
    __syncthreads();
    float Ssum = 0.f;
    #pragma unroll
    for (int i = 0; i < NS; i++) Ssum += g_ps[b*NS + i] * fac[i];
    {
        const float* pu = g_pu + (size_t)b*NS*H + tid;
        float acc = 0.f;
        #pragma unroll
        for (int i = 0; i < NS; i++)
            acc += pu[(size_t)i*H] * fac[i];
        U[tid] = acc;
    }
    __syncthreads();
    const float coef = 1.f / Ssum;   // Z cancels (non eps-corner); Ssum > 0 always
    if (tid == 0) { g_m[b] = m; g_coef[b] = coef; }
    if (tid < V) {
        const int v = tid;
        const float4* wr = (const float4*)(Wv + (size_t)v*H);
        const float4* Uv = (const float4*)U;
        float acc = 0.f;
        #pragma unroll 8
        for (int i = 0; i < H/4; i++) {
            float4 a = wr[i], xx = Uv[i];
            acc += a.x*xx.x + a.y*xx.y + a.z*xx.z + a.w*xx.w;
        }
        out[b*V + v] = acc * coef + bv[v] * (Ssum * coef);
    }
}

// ---------------- Kernel C2: attention output (wide) ----------------
__global__ void attn_out_kernel(const int* __restrict__ lens, float* __restrict__ out) {
    const int idx = blockIdx.x * 256 + threadIdx.x;  // < B*T/4
    const int base = idx * 4;
    const int b = base >> 11;        // T = 2048
    const int t = base & (T - 1);
    int len = lens[b];
    if (b == 0) len = T;
    if (len > T) len = T;
    const float4 e = ((const float4*)g_e)[idx];
    const float m = g_m[b], c = g_coef[b];
    float4 r;
    r.x = (t + 0 < len) ? __expf(e.x - m) * c : 0.f;
    r.y = (t + 1 < len) ? __expf(e.y - m) * c : 0.f;
    r.z = (t + 2 < len) ? __expf(e.z - m) * c : 0.f;
    r.w = (t + 3 < len) ? __expf(e.w - m) * c : 0.f;
    ((float4*)(out + B*V))[idx] = r;
}

extern "C" void kernel_launch(void* const* d_in, const int* in_sizes, int n_in,
                              void* d_out, int out_size) {
    const float* state = (const float*)d_in[0];
    const float* x     = (const float*)d_in[1];  // listener_output (B,T,H)
    const int*   lens  = (const int*)  d_in[2];
    const float* Ws    = (const float*)d_in[3];
    const float* bs    = (const float*)d_in[4];
    const float* Wh    = (const float*)d_in[5];
    const float* bh    = (const float*)d_in[6];
    const float* Wv    = (const float*)d_in[7];
    const float* bv    = (const float*)d_in[8];
    float* out = (float*)d_out;

    const int smem_bytes = (2*TILE*H + H + 2*TILE) * (int)sizeof(float);  // ~66 KB
    cudaFuncSetAttribute(flash_kernel, cudaFuncAttributeMaxDynamicSharedMemorySize, smem_bytes);

    prep_q_kernel<<<B, 128>>>(state, Ws, bs, bh);
    dim3 gw(2, B);
    prep_w_kernel<<<gw, 256>>>(Wh);
    dim3 grid(NS, B);
    flash_kernel<<<grid, FTHREADS, smem_bytes>>>(x, lens);
    reduce_kernel<<<B, 512>>>(Wv, bv, out);
    attn_out_kernel<<<(B*T/4)/256, 256>>>(lens, out);
}